// round 9
// baseline (speedup 1.0000x reference)
#include <cuda_runtime.h>
#include <cuda_bf16.h>
#include <cuda_fp16.h>
#include <cuda_fp8.h>
#include <cstdint>

// Problem constants
#define Bq 32
#define Dd 512
#define Tt 256
#define Nq 8192
#define Kc 8192

// GEMM tiling (fp8: BK=64 -> 64B rows)
#define BM 128
#define BN 256
#define BK 64
#define STAGES 4
#define STG_A (BM * BK)              // 8192 B
#define STG_B (BN * BK)              // 16384 B
#define STG_BYTES (STG_A + STG_B)    // 24576 B
#define KITERS (Dd / BK)             // 8

#define MARGIN 32.0f
#define MAXCAND 128
// u8 distance quantization: q = d/QSTEP, covers [0, 255*QSTEP]
#define QSTEP 4.0f
#define QINV  0.25f

// Scratch (device globals)
__device__ unsigned char g_A8[(size_t)Nq * Dd];   // queries e4m3 [n][d]
__device__ float         g_At[(size_t)Nq * Dd];   // queries fp32 [n][d]
__device__ unsigned char g_B8[(size_t)Kc * Dd];   // codebook e4m3 [c][d]
__device__ unsigned char g_D8[(size_t)Nq * Kc];   // u8 quantized distances
__device__ unsigned char g_bmin[(size_t)Nq * 32]; // per (query, nblock) u8 min
__device__ float         g_c2[Kc];
__device__ int           g_cnt[Kc];
__device__ int           g_idx[Nq];
__device__ float         g_loss;

// ---------------------------------------------------------------------------
// helpers
// ---------------------------------------------------------------------------
__device__ __forceinline__ uint32_t smem_u32(const void* p) {
    uint32_t a;
    asm("{ .reg .u64 t; cvta.to.shared.u64 t, %1; cvt.u32.u64 %0, t; }" : "=r"(a) : "l"(p));
    return a;
}
__device__ __forceinline__ void cp_async16(uint32_t s, const void* g) {
    asm volatile("cp.async.cg.shared.global [%0], [%1], 16;" :: "r"(s), "l"(g) : "memory");
}
#define CP_COMMIT() asm volatile("cp.async.commit_group;" ::: "memory")
#define CP_WAIT2()  asm volatile("cp.async.wait_group 2;" ::: "memory")
#define CP_WAIT0()  asm volatile("cp.async.wait_group 0;" ::: "memory")
#define SWZ(o) ((o) ^ (((o) >> 3) & 0x70))

__device__ __forceinline__ void ldm_x4(uint32_t& r0, uint32_t& r1, uint32_t& r2, uint32_t& r3,
                                       uint32_t a) {
    asm volatile("ldmatrix.sync.aligned.m8n8.x4.shared.b16 {%0,%1,%2,%3}, [%4];"
                 : "=r"(r0), "=r"(r1), "=r"(r2), "=r"(r3) : "r"(a));
}
__device__ __forceinline__ void mma_fp8(float* c, const uint32_t* a, const uint32_t* b) {
    asm volatile(
        "mma.sync.aligned.m16n8k32.row.col.f32.e4m3.e4m3.f32 "
        "{%0,%1,%2,%3}, {%4,%5,%6,%7}, {%8,%9}, {%0,%1,%2,%3};"
        : "+f"(c[0]), "+f"(c[1]), "+f"(c[2]), "+f"(c[3])
        : "r"(a[0]), "r"(a[1]), "r"(a[2]), "r"(a[3]), "r"(b[0]), "r"(b[1]));
}
__device__ __forceinline__ unsigned f_ord(float f) {
    unsigned u = __float_as_uint(f);
    return (u & 0x80000000u) ? ~u : (u | 0x80000000u);
}
__device__ __forceinline__ uint32_t fp8x4(float a, float b, float c, float d) {
    uint32_t lo = __nv_cvt_float2_to_fp8x2(make_float2(a, b), __NV_SATFINITE, __NV_E4M3);
    uint32_t hi = __nv_cvt_float2_to_fp8x2(make_float2(c, d), __NV_SATFINITE, __NV_E4M3);
    return lo | (hi << 16);
}
// q = d/4, clamp [0,255] -> covers d in [0, 1020]; actual d in ~[126, 898]
__device__ __forceinline__ uint32_t quant_u8(float d) {
    int q = __float2int_rn(d * QINV);
    return (uint32_t)min(255, max(0, q));
}

// ---------------------------------------------------------------------------
// 1: A build: transpose z (b,d,t) -> [n][d] fp32 + e4m3. grid (32,16), block 256
// ---------------------------------------------------------------------------
__global__ void k_convA(const float* __restrict__ z) {
    __shared__ float sm[32][257];
    int b = blockIdx.x, d0 = blockIdx.y * 32;
    int t = threadIdx.x;
    const float* zb = z + ((size_t)b * Dd + d0) * Tt;
#pragma unroll
    for (int r = 0; r < 32; r++) sm[r][t] = zb[r * Tt + t];
    __syncthreads();
    size_t row = (size_t)(b * Tt + t) * Dd + d0;
    float* pf = g_At + row;
    float v[32];
#pragma unroll
    for (int r = 0; r < 32; r++) { v[r] = sm[r][t]; pf[r] = v[r]; }
    uint32_t w[8];
#pragma unroll
    for (int q = 0; q < 8; q++)
        w[q] = fp8x4(v[4 * q], v[4 * q + 1], v[4 * q + 2], v[4 * q + 3]);
    uint4* p8 = (uint4*)(g_A8 + row);
    p8[0] = make_uint4(w[0], w[1], w[2], w[3]);
    p8[1] = make_uint4(w[4], w[5], w[6], w[7]);
}

// 2: B build: codebook -> e4m3 + exact fp32 norms + zero cnt. grid 8192, block 128
__global__ void k_convB(const float* __restrict__ cb) {
    int c = blockIdx.x, t = threadIdx.x;
    float4 v = *(const float4*)(cb + (size_t)c * Dd + 4 * t);
    *(uint32_t*)(g_B8 + (size_t)c * Dd + 4 * t) = fp8x4(v.x, v.y, v.z, v.w);
    float s = v.x * v.x + v.y * v.y + v.z * v.z + v.w * v.w;
#pragma unroll
    for (int off = 16; off; off >>= 1) s += __shfl_down_sync(0xFFFFFFFFu, s, off);
    __shared__ float ws[4];
    if ((t & 31) == 0) ws[t >> 5] = s;
    __syncthreads();
    if (t == 0) {
        g_c2[c] = ws[0] + ws[1] + ws[2] + ws[3];
        g_cnt[c] = 0;
    }
}

// 3: tiny pre-kernel (pads launch order so k_gemm is launch #4 for ncu)
__global__ void k_pre() {
    if (threadIdx.x == 0) g_loss = 0.0f;
}

// ---------------------------------------------------------------------------
// 4: e4m3 MMA GEMM 128x256x64, 8 warps, 4-stage cp.async.
//    Epilogue: dist -> u8, smem stage, coalesced store + per-block min.
//    grid (64, 32), block 256, dyn smem 96KB
// ---------------------------------------------------------------------------
__global__ __launch_bounds__(256, 1) void k_gemm() {
    extern __shared__ char smem[];
    const uint32_t sbase = smem_u32(smem);
    const int tid = threadIdx.x;
    const int wid = tid >> 5, lane = tid & 31;
    const int wm = (wid >> 2) * 64;
    const int wn = (wid & 3) * 64;
    const int m0 = blockIdx.x * BM, n0 = blockIdx.y * BN;

    const unsigned char* gA = g_A8;
    const unsigned char* gB = g_B8;

    float acc[4][8][4];
#pragma unroll
    for (int i = 0; i < 4; i++)
#pragma unroll
        for (int j = 0; j < 8; j++)
#pragma unroll
            for (int k = 0; k < 4; k++) acc[i][j][k] = 0.0f;

    auto load_stage = [&](int s, int kb) {
        uint32_t sA = sbase + s * STG_BYTES;
        uint32_t sB = sA + STG_A;
#pragma unroll
        for (int p = 0; p < 2; p++) {
            int j = tid + 256 * p;
            int r = j >> 2, c = j & 3;
            uint32_t off = r * 64 + c * 16;
            cp_async16(sA + SWZ(off), gA + (size_t)(m0 + r) * Dd + kb + c * 16);
        }
#pragma unroll
        for (int p = 0; p < 4; p++) {
            int j = tid + 256 * p;
            int r = j >> 2, c = j & 3;
            uint32_t off = r * 64 + c * 16;
            cp_async16(sB + SWZ(off), gB + (size_t)(n0 + r) * Dd + kb + c * 16);
        }
    };

    load_stage(0, 0); CP_COMMIT();
    load_stage(1, BK); CP_COMMIT();
    load_stage(2, 2 * BK); CP_COMMIT();

    for (int i = 0; i < KITERS; i++) {
        CP_WAIT2();
        __syncthreads();
        int s = i & 3;
        if (i + 3 < KITERS) load_stage((i + 3) & 3, (i + 3) * BK);
        CP_COMMIT();

        uint32_t sA = sbase + s * STG_BYTES;
        uint32_t sB = sA + STG_A;
#pragma unroll
        for (int k32 = 0; k32 < 2; k32++) {
            const int ch = 2 * k32 + (lane >> 4);
            uint32_t af[4][4], br[4][4];
#pragma unroll
            for (int mf = 0; mf < 4; mf++) {
                int r = wm + mf * 16 + (lane & 15);
                uint32_t off = r * 64 + ch * 16;
                ldm_x4(af[mf][0], af[mf][1], af[mf][2], af[mf][3], sA + SWZ(off));
            }
#pragma unroll
            for (int nf4 = 0; nf4 < 4; nf4++) {
                int r = wn + nf4 * 16 + (lane & 15);
                uint32_t off = r * 64 + ch * 16;
                ldm_x4(br[nf4][0], br[nf4][1], br[nf4][2], br[nf4][3], sB + SWZ(off));
            }
#pragma unroll
            for (int mf = 0; mf < 4; mf++)
#pragma unroll
                for (int nf4 = 0; nf4 < 4; nf4++) {
                    uint32_t b0[2] = {br[nf4][0], br[nf4][2]};
                    uint32_t b1[2] = {br[nf4][1], br[nf4][3]};
                    mma_fp8(acc[mf][2 * nf4],     af[mf], b0);
                    mma_fp8(acc[mf][2 * nf4 + 1], af[mf], b1);
                }
        }
    }

    // --- epilogue: quantize to u8, stage in smem, coalesced store + block-min
    CP_WAIT0();
    __syncthreads();                 // all in-flight stage writes done; reuse smem
    unsigned char* sD = (unsigned char*)smem;   // 128 x 256 u8 = 32KB

#pragma unroll
    for (int mf = 0; mf < 4; mf++) {
        int r0 = wm + mf * 16 + (lane >> 2);
#pragma unroll
        for (int nf = 0; nf < 8; nf++) {
            int n = wn + nf * 8 + (lane & 3) * 2;
            float c2a = g_c2[n0 + n], c2b = g_c2[n0 + n + 1];
            float* a = acc[mf][nf];
            uint32_t q00 = quant_u8(c2a - 2.0f * a[0]);
            uint32_t q01 = quant_u8(c2b - 2.0f * a[1]);
            uint32_t q10 = quant_u8(c2a - 2.0f * a[2]);
            uint32_t q11 = quant_u8(c2b - 2.0f * a[3]);
            *(unsigned short*)(sD + r0 * 256 + n)       = (unsigned short)(q00 | (q01 << 8));
            *(unsigned short*)(sD + (r0 + 8) * 256 + n) = (unsigned short)(q10 | (q11 << 8));
        }
    }
    __syncthreads();

    {
        int row = tid >> 1, seg = tid & 1;
        const uint4* src = (const uint4*)(sD + row * 256 + seg * 128);
        uint4* dst = (uint4*)(g_D8 + (size_t)(m0 + row) * Kc + n0 + seg * 128);
        uint32_t mn = 0xFFFFFFFFu;
#pragma unroll
        for (int i = 0; i < 8; i++) {
            uint4 v = src[i];
            dst[i] = v;
            mn = __vminu4(mn, __vminu4(__vminu4(v.x, v.y), __vminu4(v.z, v.w)));
        }
        uint32_t b = min(min(mn & 255u, (mn >> 8) & 255u),
                         min((mn >> 16) & 255u, mn >> 24));
        uint32_t other = __shfl_down_sync(0xFFFFFFFFu, b, 1);
        if (seg == 0)
            g_bmin[(size_t)(m0 + row) * 32 + blockIdx.y] = (unsigned char)min(b, other);
    }
}

// ---------------------------------------------------------------------------
// 5: prefiltered scan: warp per query. grid 1024, block 256
// ---------------------------------------------------------------------------
__global__ __launch_bounds__(256) void k_scan(const float* __restrict__ cb) {
    const int wid = threadIdx.x >> 5, lane = threadIdx.x & 31;
    const int q = blockIdx.x * 8 + wid;

    unsigned b = g_bmin[(size_t)q * 32 + lane];
    unsigned g = b;
#pragma unroll
    for (int off = 16; off; off >>= 1) g = min(g, __shfl_xor_sync(0xFFFFFFFFu, g, off));
    const float thr = (float)g * QSTEP + MARGIN;
    bool pass = ((float)b * QSTEP) < thr;
    unsigned mask = __ballot_sync(0xFFFFFFFFu, pass);

    __shared__ int s_cnt[8];
    __shared__ int s_cand[8][MAXCAND];
    if (lane == 0) s_cnt[wid] = 0;
    __syncwarp();

    const unsigned char* Drow = g_D8 + (size_t)q * Kc;
    while (mask) {
        int nb = __ffs(mask) - 1;
        mask &= mask - 1;
        uint2 v = *(const uint2*)(Drow + nb * 256 + lane * 8);
#pragma unroll
        for (int j = 0; j < 8; j++) {
            uint32_t byte = (j < 4) ? ((v.x >> (8 * j)) & 255u) : ((v.y >> (8 * (j - 4))) & 255u);
            if ((float)byte * QSTEP < thr) {
                int p = atomicAdd(&s_cnt[wid], 1);
                if (p < MAXCAND) s_cand[wid][p] = nb * 256 + lane * 8 + j;
            }
        }
    }
    __syncwarp();

    int nc = min(s_cnt[wid], MAXCAND);
    const float* zq = g_At + (size_t)q * Dd;
    unsigned long long best = 0xFFFFFFFFFFFFFFFFULL;
    for (int ci = 0; ci < nc; ci++) {
        int c = s_cand[wid][ci];
        const float* cr = cb + (size_t)c * Dd;
        float s = 0.0f;
#pragma unroll
        for (int d = 0; d < Dd / 32; d++)
            s = fmaf(zq[lane + d * 32], cr[lane + d * 32], s);
#pragma unroll
        for (int off = 16; off; off >>= 1) s += __shfl_down_sync(0xFFFFFFFFu, s, off);
        if (lane == 0) {
            float dex = g_c2[c] - 2.0f * s;
            unsigned long long pk = ((unsigned long long)f_ord(dex) << 32) | (unsigned)c;
            best = min(best, pk);
        }
    }
    if (lane == 0) {
        int idx = (int)(best & 0xFFFFFFFFULL);
        g_idx[q] = idx;
        atomicAdd(&g_cnt[idx], 1);
    }
}

// ---------------------------------------------------------------------------
// 6: Gather z_q to (b,d,t) + loss partials
// ---------------------------------------------------------------------------
__global__ void k_gather(const float* __restrict__ z, const float* __restrict__ cb,
                         float* __restrict__ out) {
    int bd = blockIdx.x;
    int b = bd >> 9, d = bd & 511;
    int t = threadIdx.x;
    int n = b * Tt + t;
    int idx = g_idx[n];
    size_t o = (size_t)bd * Tt + t;
    float c = cb[(size_t)idx * Dd + d];
    float zv = z[o];
    out[o] = c;
    float diff = c - zv;
    float s = diff * diff;
#pragma unroll
    for (int off = 16; off; off >>= 1) s += __shfl_down_sync(0xFFFFFFFFu, s, off);
    __shared__ float ws[8];
    if ((t & 31) == 0) ws[t >> 5] = s;
    __syncthreads();
    if (t < 8) {
        float v = ws[t];
#pragma unroll
        for (int off = 4; off; off >>= 1) v += __shfl_down_sync(0xFFu, v, off);
        if (t == 0) atomicAdd(&g_loss, v);
    }
}

// 7: Finalize loss + perplexity
__global__ void k_final(float* __restrict__ out) {
    int t = threadIdx.x;
    float local = 0.0f;
    for (int k = t; k < Kc; k += 256) {
        float p = (float)g_cnt[k] * (1.0f / (float)Nq);
        local += p * logf(p + 1e-10f);
    }
#pragma unroll
    for (int off = 16; off; off >>= 1) local += __shfl_down_sync(0xFFFFFFFFu, local, off);
    __shared__ float ws[8];
    if ((t & 31) == 0) ws[t >> 5] = local;
    __syncthreads();
    if (t == 0) {
        float tot = 0.0f;
#pragma unroll
        for (int i = 0; i < 8; i++) tot += ws[i];
        size_t base = (size_t)Bq * Dd * Tt;
        out[base]     = 0.25f * g_loss / (float)((size_t)Nq * Dd);
        out[base + 1] = expf(-tot);
    }
}

// ---------------------------------------------------------------------------
extern "C" void kernel_launch(void* const* d_in, const int* in_sizes, int n_in,
                              void* d_out, int out_size) {
    const float* z  = (const float*)d_in[0];
    const float* cb = (const float*)d_in[1];
    float* out = (float*)d_out;
    (void)in_sizes; (void)n_in; (void)out_size;

    cudaFuncSetAttribute(k_gemm, cudaFuncAttributeMaxDynamicSharedMemorySize,
                         STAGES * STG_BYTES);

    k_convA<<<dim3(32, 16), 256>>>(z);        // launch 1
    k_convB<<<Kc, 128>>>(cb);                 // launch 2
    k_pre<<<1, 32>>>();                       // launch 3
    k_gemm<<<dim3(Nq / BM, Kc / BN), 256, STAGES * STG_BYTES>>>();  // launch 4 (ncu)
    k_scan<<<1024, 256>>>(cb);                // launch 5
    k_gather<<<Bq * Dd, 256>>>(z, cb, out);   // launch 6
    k_final<<<1, 256>>>(out);                 // launch 7
}

// round 13
// speedup vs baseline: 1.0067x; 1.0067x over previous
#include <cuda_runtime.h>
#include <cuda_bf16.h>
#include <cuda_fp16.h>
#include <cuda_fp8.h>
#include <cstdint>

// Problem constants
#define Bq 32
#define Dd 512
#define Tt 256
#define Nq 8192
#define Kc 8192

// GEMM tiling (fp8: BK=64 -> 64B rows)
#define BM 128
#define BN 256
#define BK 64
#define STAGES 4
#define STG_A (BM * BK)              // 8192 B
#define STG_B (BN * BK)              // 16384 B
#define STG_BYTES (STG_A + STG_B)    // 24576 B
#define KITERS (Dd / BK)             // 8
#define NTHREADS 512

#define MARGIN 32.0f
#define MAXCAND 128
// u8 distance quantization: q = d/QSTEP
#define QSTEP 4.0f
#define QINV  0.25f

// Scratch (device globals)
__device__ unsigned char g_A8[(size_t)Nq * Dd];   // queries e4m3 [n][d]
__device__ float         g_At[(size_t)Nq * Dd];   // queries fp32 [n][d]
__device__ unsigned char g_B8[(size_t)Kc * Dd];   // codebook e4m3 [c][d]
__device__ unsigned char g_D8[(size_t)Nq * Kc];   // u8 quantized distances
__device__ unsigned char g_bmin[(size_t)Nq * 32]; // per (query, nblock) u8 min
__device__ float         g_c2[Kc];
__device__ int           g_cnt[Kc];
__device__ int           g_idx[Nq];
__device__ float         g_loss;

// ---------------------------------------------------------------------------
// helpers
// ---------------------------------------------------------------------------
__device__ __forceinline__ uint32_t smem_u32(const void* p) {
    uint32_t a;
    asm("{ .reg .u64 t; cvta.to.shared.u64 t, %1; cvt.u32.u64 %0, t; }" : "=r"(a) : "l"(p));
    return a;
}
__device__ __forceinline__ void cp_async16(uint32_t s, const void* g) {
    asm volatile("cp.async.cg.shared.global [%0], [%1], 16;" :: "r"(s), "l"(g) : "memory");
}
#define CP_COMMIT() asm volatile("cp.async.commit_group;" ::: "memory")
#define CP_WAIT2()  asm volatile("cp.async.wait_group 2;" ::: "memory")
#define CP_WAIT0()  asm volatile("cp.async.wait_group 0;" ::: "memory")
#define SWZ(o) ((o) ^ (((o) >> 3) & 0x70))

__device__ __forceinline__ void ldm_x4(uint32_t& r0, uint32_t& r1, uint32_t& r2, uint32_t& r3,
                                       uint32_t a) {
    asm volatile("ldmatrix.sync.aligned.m8n8.x4.shared.b16 {%0,%1,%2,%3}, [%4];"
                 : "=r"(r0), "=r"(r1), "=r"(r2), "=r"(r3) : "r"(a));
}
__device__ __forceinline__ void mma_fp8(float* c, const uint32_t* a, const uint32_t* b) {
    asm volatile(
        "mma.sync.aligned.m16n8k32.row.col.f32.e4m3.e4m3.f32 "
        "{%0,%1,%2,%3}, {%4,%5,%6,%7}, {%8,%9}, {%0,%1,%2,%3};"
        : "+f"(c[0]), "+f"(c[1]), "+f"(c[2]), "+f"(c[3])
        : "r"(a[0]), "r"(a[1]), "r"(a[2]), "r"(a[3]), "r"(b[0]), "r"(b[1]));
}
__device__ __forceinline__ unsigned f_ord(float f) {
    unsigned u = __float_as_uint(f);
    return (u & 0x80000000u) ? ~u : (u | 0x80000000u);
}
__device__ __forceinline__ uint32_t fp8x4(float a, float b, float c, float d) {
    uint32_t lo = __nv_cvt_float2_to_fp8x2(make_float2(a, b), __NV_SATFINITE, __NV_E4M3);
    uint32_t hi = __nv_cvt_float2_to_fp8x2(make_float2(c, d), __NV_SATFINITE, __NV_E4M3);
    return lo | (hi << 16);
}
__device__ __forceinline__ uint32_t quant_u8(float d) {
    int q = __float2int_rn(d * QINV);
    return (uint32_t)min(255, max(0, q));
}

// ---------------------------------------------------------------------------
// 1: A build: transpose z (b,d,t) -> [n][d] fp32 + e4m3. grid (32,16), block 256
// ---------------------------------------------------------------------------
__global__ void k_convA(const float* __restrict__ z) {
    __shared__ float sm[32][257];
    int b = blockIdx.x, d0 = blockIdx.y * 32;
    int t = threadIdx.x;
    const float* zb = z + ((size_t)b * Dd + d0) * Tt;
#pragma unroll
    for (int r = 0; r < 32; r++) sm[r][t] = zb[r * Tt + t];
    __syncthreads();
    size_t row = (size_t)(b * Tt + t) * Dd + d0;
    float* pf = g_At + row;
    float v[32];
#pragma unroll
    for (int r = 0; r < 32; r++) { v[r] = sm[r][t]; pf[r] = v[r]; }
    uint32_t w[8];
#pragma unroll
    for (int q = 0; q < 8; q++)
        w[q] = fp8x4(v[4 * q], v[4 * q + 1], v[4 * q + 2], v[4 * q + 3]);
    uint4* p8 = (uint4*)(g_A8 + row);
    p8[0] = make_uint4(w[0], w[1], w[2], w[3]);
    p8[1] = make_uint4(w[4], w[5], w[6], w[7]);
}

// 2: B build: codebook -> e4m3 + exact fp32 norms + zero cnt. grid 8192, block 128
__global__ void k_convB(const float* __restrict__ cb) {
    int c = blockIdx.x, t = threadIdx.x;
    float4 v = *(const float4*)(cb + (size_t)c * Dd + 4 * t);
    *(uint32_t*)(g_B8 + (size_t)c * Dd + 4 * t) = fp8x4(v.x, v.y, v.z, v.w);
    float s = v.x * v.x + v.y * v.y + v.z * v.z + v.w * v.w;
#pragma unroll
    for (int off = 16; off; off >>= 1) s += __shfl_down_sync(0xFFFFFFFFu, s, off);
    __shared__ float ws[4];
    if ((t & 31) == 0) ws[t >> 5] = s;
    __syncthreads();
    if (t == 0) {
        g_c2[c] = ws[0] + ws[1] + ws[2] + ws[3];
        g_cnt[c] = 0;
    }
}

// 3: tiny pre-kernel (pads launch order so k_gemm is launch #4 for ncu)
__global__ void k_pre() {
    if (threadIdx.x == 0) g_loss = 0.0f;
}

// ---------------------------------------------------------------------------
// 4: e4m3 MMA GEMM 128x256x64, 16 warps (4x4, warp tile 32x64), 4-stage cp.async.
//    Epilogue: dist -> u8, smem stage, coalesced store + per-block min.
//    grid (64, 32), block 512, dyn smem 96KB
// ---------------------------------------------------------------------------
__global__ __launch_bounds__(NTHREADS, 1) void k_gemm() {
    extern __shared__ char smem[];
    const uint32_t sbase = smem_u32(smem);
    const int tid = threadIdx.x;
    const int wid = tid >> 5, lane = tid & 31;
    const int wm = (wid & 3) * 32;        // warp m offset (0/32/64/96)
    const int wn = (wid >> 2) * 64;       // warp n offset (0/64/128/192)
    const int m0 = blockIdx.x * BM, n0 = blockIdx.y * BN;

    const unsigned char* gA = g_A8;
    const unsigned char* gB = g_B8;

    float acc[2][8][4];
#pragma unroll
    for (int i = 0; i < 2; i++)
#pragma unroll
        for (int j = 0; j < 8; j++)
#pragma unroll
            for (int k = 0; k < 4; k++) acc[i][j][k] = 0.0f;

    auto load_stage = [&](int s, int kb) {
        uint32_t sA = sbase + s * STG_BYTES;
        uint32_t sB = sA + STG_A;
        {   // A: 512 chunks of 16B, one per thread
            int r = tid >> 2, c = tid & 3;
            uint32_t off = r * 64 + c * 16;
            cp_async16(sA + SWZ(off), gA + (size_t)(m0 + r) * Dd + kb + c * 16);
        }
#pragma unroll
        for (int p = 0; p < 2; p++) {     // B: 1024 chunks
            int j = tid + NTHREADS * p;
            int r = j >> 2, c = j & 3;
            uint32_t off = r * 64 + c * 16;
            cp_async16(sB + SWZ(off), gB + (size_t)(n0 + r) * Dd + kb + c * 16);
        }
    };

    load_stage(0, 0); CP_COMMIT();
    load_stage(1, BK); CP_COMMIT();
    load_stage(2, 2 * BK); CP_COMMIT();

    for (int i = 0; i < KITERS; i++) {
        CP_WAIT2();
        __syncthreads();
        int s = i & 3;
        if (i + 3 < KITERS) load_stage((i + 3) & 3, (i + 3) * BK);
        CP_COMMIT();

        uint32_t sA = sbase + s * STG_BYTES;
        uint32_t sB = sA + STG_A;
#pragma unroll
        for (int k32 = 0; k32 < 2; k32++) {
            const int ch = 2 * k32 + (lane >> 4);
            uint32_t af[2][4], br[4][4];
#pragma unroll
            for (int mf = 0; mf < 2; mf++) {
                int r = wm + mf * 16 + (lane & 15);
                uint32_t off = r * 64 + ch * 16;
                ldm_x4(af[mf][0], af[mf][1], af[mf][2], af[mf][3], sA + SWZ(off));
            }
#pragma unroll
            for (int nf4 = 0; nf4 < 4; nf4++) {
                int r = wn + nf4 * 16 + (lane & 15);
                uint32_t off = r * 64 + ch * 16;
                ldm_x4(br[nf4][0], br[nf4][1], br[nf4][2], br[nf4][3], sB + SWZ(off));
            }
#pragma unroll
            for (int mf = 0; mf < 2; mf++)
#pragma unroll
                for (int nf4 = 0; nf4 < 4; nf4++) {
                    uint32_t b0[2] = {br[nf4][0], br[nf4][2]};
                    uint32_t b1[2] = {br[nf4][1], br[nf4][3]};
                    mma_fp8(acc[mf][2 * nf4],     af[mf], b0);
                    mma_fp8(acc[mf][2 * nf4 + 1], af[mf], b1);
                }
        }
    }

    // --- epilogue: quantize to u8, stage in smem, coalesced store + block-min
    CP_WAIT0();
    __syncthreads();                 // in-flight stage writes done; reuse smem
    unsigned char* sD = (unsigned char*)smem;   // 128 x 256 u8 = 32KB

#pragma unroll
    for (int mf = 0; mf < 2; mf++) {
        int r0 = wm + mf * 16 + (lane >> 2);
#pragma unroll
        for (int nf = 0; nf < 8; nf++) {
            int n = wn + nf * 8 + (lane & 3) * 2;
            float c2a = g_c2[n0 + n], c2b = g_c2[n0 + n + 1];
            float* a = acc[mf][nf];
            uint32_t q00 = quant_u8(c2a - 2.0f * a[0]);
            uint32_t q01 = quant_u8(c2b - 2.0f * a[1]);
            uint32_t q10 = quant_u8(c2a - 2.0f * a[2]);
            uint32_t q11 = quant_u8(c2b - 2.0f * a[3]);
            *(unsigned short*)(sD + r0 * 256 + n)       = (unsigned short)(q00 | (q01 << 8));
            *(unsigned short*)(sD + (r0 + 8) * 256 + n) = (unsigned short)(q10 | (q11 << 8));
        }
    }
    __syncthreads();

    {
        int row = tid >> 2, seg = tid & 3;   // 4 threads per 256B row
        const uint4* src = (const uint4*)(sD + row * 256 + seg * 64);
        uint4* dst = (uint4*)(g_D8 + (size_t)(m0 + row) * Kc + n0 + seg * 64);
        uint32_t mn = 0xFFFFFFFFu;
#pragma unroll
        for (int i = 0; i < 4; i++) {
            uint4 v = src[i];
            dst[i] = v;
            mn = __vminu4(mn, __vminu4(__vminu4(v.x, v.y), __vminu4(v.z, v.w)));
        }
        uint32_t b = min(min(mn & 255u, (mn >> 8) & 255u),
                         min((mn >> 16) & 255u, mn >> 24));
        b = min(b, __shfl_down_sync(0xFFFFFFFFu, b, 2));
        b = min(b, __shfl_down_sync(0xFFFFFFFFu, b, 1));
        if (seg == 0)
            g_bmin[(size_t)(m0 + row) * 32 + blockIdx.y] = (unsigned char)b;
    }
}

// ---------------------------------------------------------------------------
// 5: prefiltered scan: warp per query. grid 1024, block 256
// ---------------------------------------------------------------------------
__global__ __launch_bounds__(256) void k_scan(const float* __restrict__ cb) {
    const int wid = threadIdx.x >> 5, lane = threadIdx.x & 31;
    const int q = blockIdx.x * 8 + wid;

    unsigned b = g_bmin[(size_t)q * 32 + lane];
    unsigned g = b;
#pragma unroll
    for (int off = 16; off; off >>= 1) g = min(g, __shfl_xor_sync(0xFFFFFFFFu, g, off));
    const float thr = (float)g * QSTEP + MARGIN;
    bool pass = ((float)b * QSTEP) < thr;
    unsigned mask = __ballot_sync(0xFFFFFFFFu, pass);

    __shared__ int s_cnt[8];
    __shared__ int s_cand[8][MAXCAND];
    if (lane == 0) s_cnt[wid] = 0;
    __syncwarp();

    const unsigned char* Drow = g_D8 + (size_t)q * Kc;
    while (mask) {
        int nb = __ffs(mask) - 1;
        mask &= mask - 1;
        uint2 v = *(const uint2*)(Drow + nb * 256 + lane * 8);
#pragma unroll
        for (int j = 0; j < 8; j++) {
            uint32_t byte = (j < 4) ? ((v.x >> (8 * j)) & 255u) : ((v.y >> (8 * (j - 4))) & 255u);
            if ((float)byte * QSTEP < thr) {
                int p = atomicAdd(&s_cnt[wid], 1);
                if (p < MAXCAND) s_cand[wid][p] = nb * 256 + lane * 8 + j;
            }
        }
    }
    __syncwarp();

    int nc = min(s_cnt[wid], MAXCAND);
    const float* zq = g_At + (size_t)q * Dd;
    unsigned long long best = 0xFFFFFFFFFFFFFFFFULL;
    for (int ci = 0; ci < nc; ci++) {
        int c = s_cand[wid][ci];
        const float* cr = cb + (size_t)c * Dd;
        float s = 0.0f;
#pragma unroll
        for (int d = 0; d < Dd / 32; d++)
            s = fmaf(zq[lane + d * 32], cr[lane + d * 32], s);
#pragma unroll
        for (int off = 16; off; off >>= 1) s += __shfl_down_sync(0xFFFFFFFFu, s, off);
        if (lane == 0) {
            float dex = g_c2[c] - 2.0f * s;
            unsigned long long pk = ((unsigned long long)f_ord(dex) << 32) | (unsigned)c;
            best = min(best, pk);
        }
    }
    if (lane == 0) {
        int idx = (int)(best & 0xFFFFFFFFULL);
        g_idx[q] = idx;
        atomicAdd(&g_cnt[idx], 1);
    }
}

// ---------------------------------------------------------------------------
// 6: Gather z_q to (b,d,t) + loss partials
// ---------------------------------------------------------------------------
__global__ void k_gather(const float* __restrict__ z, const float* __restrict__ cb,
                         float* __restrict__ out) {
    int bd = blockIdx.x;
    int b = bd >> 9, d = bd & 511;
    int t = threadIdx.x;
    int n = b * Tt + t;
    int idx = g_idx[n];
    size_t o = (size_t)bd * Tt + t;
    float c = cb[(size_t)idx * Dd + d];
    float zv = z[o];
    out[o] = c;
    float diff = c - zv;
    float s = diff * diff;
#pragma unroll
    for (int off = 16; off; off >>= 1) s += __shfl_down_sync(0xFFFFFFFFu, s, off);
    __shared__ float ws[8];
    if ((t & 31) == 0) ws[t >> 5] = s;
    __syncthreads();
    if (t < 8) {
        float v = ws[t];
#pragma unroll
        for (int off = 4; off; off >>= 1) v += __shfl_down_sync(0xFFu, v, off);
        if (t == 0) atomicAdd(&g_loss, v);
    }
}

// 7: Finalize loss + perplexity
__global__ void k_final(float* __restrict__ out) {
    int t = threadIdx.x;
    float local = 0.0f;
    for (int k = t; k < Kc; k += 256) {
        float p = (float)g_cnt[k] * (1.0f / (float)Nq);
        local += p * logf(p + 1e-10f);
    }
#pragma unroll
    for (int off = 16; off; off >>= 1) local += __shfl_down_sync(0xFFFFFFFFu, local, off);
    __shared__ float ws[8];
    if ((t & 31) == 0) ws[t >> 5] = local;
    __syncthreads();
    if (t == 0) {
        float tot = 0.0f;
#pragma unroll
        for (int i = 0; i < 8; i++) tot += ws[i];
        size_t base = (size_t)Bq * Dd * Tt;
        out[base]     = 0.25f * g_loss / (float)((size_t)Nq * Dd);
        out[base + 1] = expf(-tot);
    }
}

// ---------------------------------------------------------------------------
extern "C" void kernel_launch(void* const* d_in, const int* in_sizes, int n_in,
                              void* d_out, int out_size) {
    const float* z  = (const float*)d_in[0];
    const float* cb = (const float*)d_in[1];
    float* out = (float*)d_out;
    (void)in_sizes; (void)n_in; (void)out_size;

    cudaFuncSetAttribute(k_gemm, cudaFuncAttributeMaxDynamicSharedMemorySize,
                         STAGES * STG_BYTES);

    k_convA<<<dim3(32, 16), 256>>>(z);        // launch 1
    k_convB<<<Kc, 128>>>(cb);                 // launch 2
    k_pre<<<1, 32>>>();                       // launch 3
    k_gemm<<<dim3(Nq / BM, Kc / BN), NTHREADS, STAGES * STG_BYTES>>>();  // launch 4 (ncu)
    k_scan<<<1024, 256>>>(cb);                // launch 5
    k_gather<<<Bq * Dd, 256>>>(z, cb, out);   // launch 6
    k_final<<<1, 256>>>(out);                 // launch 7
}